// round 4
// baseline (speedup 1.0000x reference)
#include <cuda_runtime.h>
#include <cuda_bf16.h>
#include <cstdint>

// ---------------- problem constants ----------------
#define BATCH 8
#define CIN 512
#define HH 50
#define WW 50
#define NPX (HH*WW)          // 2500
#define NA 9
#define NANCH (NPX*NA)       // 22500
#define PRE_NMS 1000
#define POST_NMS 300
#define NMS_THR 0.7f
#define IMGF 800.0f
#define MIN_SIZE 16.0f

// ---------------- device scratch (static; no allocations allowed) ----------------
__device__ float g_feat[(size_t)BATCH*CIN*NPX];     // shared conv output (relu'd)
__device__ float g_boxes[(size_t)BATCH*NANCH*4];
__device__ unsigned int g_key[(size_t)BATCH*NANCH]; // monotone score key (0 == invalid)

// ============================================================
// Kernel 1: 3x3 conv 512->512, SAME, +bias, ReLU, fp32
// Double-buffered smem; two-level accumulation (identical FMA order
// to the round-3 passing kernel => bitwise identical output).
// block: 256 threads, tile 64 out-ch x (2 rows x 64 cols); thread: 4k x 8px
// ============================================================
#define CONV_SMEM (2*(8*4*66 + 8*64*9)*4)   // 53760 bytes

__global__ __launch_bounds__(256) void conv3x3_kernel(
    const float* __restrict__ x, const float* __restrict__ w, const float* __restrict__ bias)
{
    extern __shared__ float cs[];
    float* sIn = cs;            // [2][8][4][66]  buf*2112 + c*264 + r*66 + xx
    float* sW  = cs + 2*2112;   // [2][8][64][9]  buf*4608 + c*576 + k*9 + q

    const int r0 = blockIdx.x * 2;    // output row pair
    const int k0 = blockIdx.y * 64;
    const int b  = blockIdx.z;
    const int tid = threadIdx.x;
    const int kg = tid >> 4;          // 0..15, 4 k each
    const int pxg = tid & 15;         // 0..15, 8 px each (2 rows x 4 cols strided 16)

    float tot[4][8];
#pragma unroll
    for (int jj = 0; jj < 4; ++jj)
#pragma unroll
        for (int i = 0; i < 8; ++i) tot[jj][i] = 0.f;

    const float* xb = x + (size_t)b * CIN * NPX;

    // ---- loader (chunk ch into buffer buf) ----
    auto load_chunk = [&](int ch, int buf) {
        const int c0 = ch * 8;
        float* dIn = sIn + buf * 2112;
        float* dW  = sW  + buf * 4608;
        for (int idx = tid; idx < 8 * 4 * 66; idx += 256) {
            int c = idx / 264; int rem = idx % 264;
            int r = rem / 66;  int xx = rem % 66;
            int gy = r0 - 1 + r;
            int gx = xx - 1;
            float v = 0.f;
            if ((unsigned)gy < (unsigned)HH && (unsigned)gx < (unsigned)WW)
                v = xb[(size_t)(c0 + c) * NPX + gy * WW + gx];
            dIn[idx] = v;
        }
        for (int idx = tid; idx < 8 * 64 * 9; idx += 256) {
            int c = idx / 576; int rem = idx % 576;
            int k = rem / 9;   int q = rem % 9;
            dW[idx] = w[(size_t)(k0 + k) * (CIN * 9) + (size_t)(c0 + c) * 9 + q];
        }
    };

    load_chunk(0, 0);
    __syncthreads();

    for (int ch = 0; ch < CIN / 8; ++ch) {
        const int cur = ch & 1;
        if (ch + 1 < CIN / 8) load_chunk(ch + 1, cur ^ 1);

        const float* bIn = sIn + cur * 2112;
        const float* bW  = sW  + cur * 4608;

        // chunk accumulators (reset per 8-channel chunk)
        float acc[4][8];
#pragma unroll
        for (int jj = 0; jj < 4; ++jj)
#pragma unroll
            for (int i = 0; i < 8; ++i) acc[jj][i] = 0.f;

        for (int c = 0; c < 8; ++c) {
#pragma unroll
            for (int dy = 0; dy < 3; ++dy) {
#pragma unroll
                for (int dx = 0; dx < 3; ++dx) {
                    float wv[4], iv[8];
#pragma unroll
                    for (int jj = 0; jj < 4; ++jj)
                        wv[jj] = bW[c * 576 + (kg * 4 + jj) * 9 + dy * 3 + dx];
#pragma unroll
                    for (int i = 0; i < 8; ++i) {
                        int row = i >> 2;
                        int col = pxg + (i & 3) * 16;
                        iv[i] = bIn[c * 264 + (row + dy) * 66 + col + dx];
                    }
#pragma unroll
                    for (int jj = 0; jj < 4; ++jj)
#pragma unroll
                        for (int i = 0; i < 8; ++i)
                            acc[jj][i] = fmaf(wv[jj], iv[i], acc[jj][i]);
                }
            }
        }
        // fold chunk into totals
#pragma unroll
        for (int jj = 0; jj < 4; ++jj)
#pragma unroll
            for (int i = 0; i < 8; ++i) tot[jj][i] += acc[jj][i];

        __syncthreads();
    }

    // epilogue: bias + relu + store
#pragma unroll
    for (int i = 0; i < 8; ++i) {
        int row = r0 + (i >> 2);
        int col = pxg + (i & 3) * 16;
        if (col < WW) {
#pragma unroll
            for (int jj = 0; jj < 4; ++jj) {
                int k = k0 + kg * 4 + jj;
                float v = tot[jj][i] + bias[k];
                v = fmaxf(v, 0.f);
                g_feat[((size_t)b * CIN + k) * NPX + row * WW + col] = v;
            }
        }
    }
}

// ============================================================
// Kernel 2: fused 1x1 heads (cls 18 + reg 36) + anchor decode.
// block handles 32 pixels of one image; X staged in 64KB dynamic smem.
// Head math identical to round-3 passing kernel (two-level accumulation).
// ============================================================
__global__ __launch_bounds__(256) void heads_decode_kernel(
    const float* __restrict__ wc, const float* __restrict__ bc,
    const float* __restrict__ wr, const float* __restrict__ brg)
{
    extern __shared__ float X[];            // [512][32]
    __shared__ float scls[32 * 18];
    __shared__ float sreg[32 * 36];

    const int b = blockIdx.y;
    const int p0 = blockIdx.x * 32;
    const int tid = threadIdx.x;

    for (int idx = tid; idx < CIN * 32; idx += 256) {
        int c = idx >> 5; int j = idx & 31;
        int p = p0 + j;
        X[idx] = (p < NPX) ? g_feat[((size_t)b * CIN + c) * NPX + p] : 0.f;
    }
    __syncthreads();

    for (int t = tid; t < 54 * 8; t += 256) {
        int o = t >> 3;
        int j0 = (t & 7) * 4;
        float bb = (o < 18) ? bc[o] : brg[o - 18];
        const float* W = (o < 18) ? (wc + (size_t)o * CIN) : (wr + (size_t)(o - 18) * CIN);
        float t0 = 0.f, t1 = 0.f, t2 = 0.f, t3 = 0.f;
        for (int cc = 0; cc < CIN; cc += 8) {
            float a0 = 0.f, a1 = 0.f, a2 = 0.f, a3 = 0.f;
#pragma unroll
            for (int u = 0; u < 8; ++u) {
                int c = cc + u;
                float wv = __ldg(&W[c]);
                const float4 xv = *(const float4*)&X[c * 32 + j0];
                a0 = fmaf(wv, xv.x, a0);
                a1 = fmaf(wv, xv.y, a1);
                a2 = fmaf(wv, xv.z, a2);
                a3 = fmaf(wv, xv.w, a3);
            }
            t0 += a0; t1 += a1; t2 += a2; t3 += a3;
        }
        float accs[4] = {t0 + bb, t1 + bb, t2 + bb, t3 + bb};
#pragma unroll
        for (int jj = 0; jj < 4; ++jj) {
            int j = j0 + jj;
            if (o < 18) scls[j * 18 + o] = accs[jj];
            else        sreg[j * 36 + (o - 18)] = accs[jj];
        }
    }
    __syncthreads();

    // decode 32*9 = 288 anchors
    for (int t = tid; t < 32 * NA; t += 256) {
        int j = t / NA;
        int a = t % NA;
        int p = p0 + j;
        if (p >= NPX) continue;
        int yy = p / WW;
        int xx = p % WW;

        int ri = a / 3, si = a % 3;
        float ratio = (ri == 0) ? 0.5f : (ri == 1 ? 1.0f : 2.0f);
        float scale = (si == 0) ? 8.0f : (si == 1 ? 16.0f : 32.0f);
        float ah = 16.0f * scale * sqrtf(ratio);
        float aw = 16.0f * scale * sqrtf(1.0f / ratio);
        float sy = yy * 16.0f, sx = xx * 16.0f;
        float ay1 = sy + 8.0f - ah * 0.5f;
        float ax1 = sx + 8.0f - aw * 0.5f;
        float ay2 = sy + 8.0f + ah * 0.5f;
        float ax2 = sx + 8.0f + aw * 0.5f;

        float h = ay2 - ay1;
        float w = ax2 - ax1;
        float cy = ay1 + 0.5f * h;
        float cx = ax1 + 0.5f * w;

        const float* rg = &sreg[j * 36 + a * 4];
        float ncy = rg[0] * h + cy;
        float ncx = rg[1] * w + cx;
        float nh = h * expf(rg[2]);
        float nw = w * expf(rg[3]);

        float y1 = fminf(fmaxf(ncy - 0.5f * nh, 0.f), IMGF);
        float x1 = fminf(fmaxf(ncx - 0.5f * nw, 0.f), IMGF);
        float y2 = fminf(fmaxf(ncy + 0.5f * nh, 0.f), IMGF);
        float x2 = fminf(fmaxf(ncx + 0.5f * nw, 0.f), IMGF);

        float hs = y2 - y1, ws = x2 - x1;
        bool valid = (hs >= MIN_SIZE) && (ws >= MIN_SIZE);

        float c0 = scls[j * 18 + a * 2 + 0], c1 = scls[j * 18 + a * 2 + 1];
        float m = fmaxf(c0, c1);
        float e0 = expf(c0 - m);
        float e1 = expf(c1 - m);
        float score = e1 / (e0 + e1);

        int n = p * NA + a;
        float* bx = &g_boxes[((size_t)b * NANCH + n) * 4];
        bx[0] = y1; bx[1] = x1; bx[2] = y2; bx[3] = x2;
        g_key[(size_t)b * NANCH + n] = valid ? (__float_as_uint(score) | 0x80000000u) : 0u;
    }
}

// ============================================================
// Kernel 3: per-image top-1000 select + sort + bitmask NMS + top-300 output
// one block (1024 threads) per image
// smem layout (phased reuse):
//   phase1: skey   u32[22500]           @ 0       .. 90000
//           cand   u64[2048]            @ 90112   .. 106496
//   phase2: sb     f32[1000][4]         @ 0       .. 16000
//           sarea  f32[1000]            @ 16000   .. 20000
//           sscore f32[1000]            @ 20000   .. 24000
//           mask   u32[1000][32]        @ 24000   .. 152000
//           sA,sB  i32[1024] each       @ 152064  .. 160256
// ============================================================
#define PROP_SMEM 160256

__global__ __launch_bounds__(1024) void propose_kernel(float* __restrict__ out)
{
    extern __shared__ unsigned char smem[];
    unsigned int* skey = (unsigned int*)smem;
    unsigned long long* cand = (unsigned long long*)(smem + 90112);
    float* sb     = (float*)smem;
    float* sarea  = (float*)(smem + 16000);
    float* sscore = (float*)(smem + 20000);
    unsigned int* mask = (unsigned int*)(smem + 24000);
    int* sA = (int*)(smem + 152064);
    int* sB = (int*)(smem + 152064 + 4096);
    __shared__ int s_cnt;
    __shared__ unsigned int s_T;
    __shared__ int s_nc;
    __shared__ int s_NK;
    __shared__ unsigned int kw[32];

    const int b = blockIdx.x;
    const int tid = threadIdx.x;
    const int wid = tid >> 5;
    const int lane = tid & 31;
    const unsigned int* gk = g_key + (size_t)b * NANCH;

    for (int n = tid; n < NANCH; n += 1024) skey[n] = gk[n];
    if (tid == 0) s_T = 0u;
    __syncthreads();

    // exact 1000th-largest key via bitwise binary search
    for (int bit = 31; bit >= 0; --bit) {
        unsigned int T2 = s_T | (1u << bit);
        if (tid == 0) s_cnt = 0;
        __syncthreads();
        int c = 0;
        for (int n = tid; n < NANCH; n += 1024) c += (skey[n] >= T2) ? 1 : 0;
#pragma unroll
        for (int o = 16; o; o >>= 1) c += __shfl_down_sync(0xFFFFFFFFu, c, o);
        if (lane == 0) atomicAdd(&s_cnt, c);
        __syncthreads();
        if (tid == 0 && s_cnt >= PRE_NMS) s_T = T2;
        __syncthreads();
    }
    unsigned int T = s_T;
    if (tid == 0) s_nc = 0;
    __syncthreads();

    // gather candidates (key >= T), packed (key << 32) | ~idx for stable tie-break
    for (int n = tid; n < NANCH; n += 1024) {
        unsigned int k = skey[n];
        if (k >= T) {
            int pos = atomicAdd(&s_nc, 1);
            if (pos < 2048)
                cand[pos] = ((unsigned long long)k << 32) | (unsigned int)(~n);
        }
    }
    __syncthreads();
    int nc = min(s_nc, 2048);
    for (int i = tid; i < 2048; i += 1024)
        if (i >= nc) cand[i] = 0ull;
    __syncthreads();

    // bitonic sort 2048, descending
    for (int k = 2; k <= 2048; k <<= 1) {
        for (int j = k >> 1; j > 0; j >>= 1) {
            __syncthreads();
#pragma unroll
            for (int base = 0; base < 2048; base += 1024) {
                int i = base + tid;
                int ixj = i ^ j;
                if (ixj > i) {
                    unsigned long long a = cand[i], c2 = cand[ixj];
                    bool up = ((i & k) == 0);
                    bool swap = up ? (a < c2) : (a > c2);
                    if (swap) { cand[i] = c2; cand[ixj] = a; }
                }
            }
        }
    }
    __syncthreads();

    // load top-1000 boxes (overwrites skey region; cand region untouched)
    float myScore = 0.f;
    if (tid < PRE_NMS) {
        unsigned long long ck = cand[tid];
        unsigned int idx = ~(unsigned int)(ck & 0xFFFFFFFFull);
        if (idx >= (unsigned)NANCH) idx = 0;
        const float* bx = g_boxes + ((size_t)b * NANCH + idx) * 4;
        float y1 = bx[0], x1 = bx[1], y2 = bx[2], x2 = bx[3];
        sb[tid * 4 + 0] = y1; sb[tid * 4 + 1] = x1;
        sb[tid * 4 + 2] = y2; sb[tid * 4 + 3] = x2;
        sarea[tid] = (y2 - y1) * (x2 - x1);
        unsigned int kb = (unsigned int)(ck >> 32);
        myScore = __uint_as_float(kb ^ 0x80000000u);
        sscore[tid] = myScore;
    }
    __syncthreads();

    // suppression bitmask matrix: warp per row i, ballot over 32-j words
    for (int i = wid; i < PRE_NMS; i += 32) {
        const float4 bi = ((const float4*)sb)[i];
        const float ai = sarea[i];
#pragma unroll 4
        for (int w0 = 0; w0 < 32; ++w0) {
            int j = w0 * 32 + lane;
            bool sup = false;
            if (j > i && j < PRE_NMS) {
                const float4 bj = ((const float4*)sb)[j];
                float ty = fmaxf(bi.x, bj.x);
                float tx = fmaxf(bi.y, bj.y);
                float by = fminf(bi.z, bj.z);
                float bxx = fminf(bi.w, bj.w);
                float ih = fmaxf(by - ty, 0.f);
                float iw = fmaxf(bxx - tx, 0.f);
                float inter = ih * iw;
                float iou = inter / (ai + sarea[j] - inter + 1e-9f);
                sup = iou > NMS_THR;
            }
            unsigned int word = __ballot_sync(0xFFFFFFFFu, sup);
            if (lane == 0) mask[i * 32 + w0] = word;
        }
    }
    if (tid < 32) kw[tid] = 0xFFFFFFFFu;
    __syncthreads();

    // serial greedy scan over bit rows (warp 0) — exact reference semantics
    if (tid < 32) {
        for (int i = 0; i < PRE_NMS; ++i) {
            unsigned int w = kw[i >> 5];
            if ((w >> (i & 31)) & 1u)
                kw[tid] &= ~mask[i * 32 + tid];
            __syncwarp();
        }
    }
    __syncthreads();

    // keep flags + inclusive prefix sum (Hillis-Steele)
    int keepv = (tid < PRE_NMS) ? (int)((kw[tid >> 5] >> (tid & 31)) & 1u) : 0;
    sA[tid] = keepv;
    __syncthreads();
    int* src = sA; int* dst = sB;
    for (int d = 1; d < 1024; d <<= 1) {
        int v = src[tid];
        if (tid >= d) v += src[tid - d];
        dst[tid] = v;
        __syncthreads();
        int* t = src; src = dst; dst = t;
    }
    if (tid == 0) s_NK = src[PRE_NMS - 1];
    __syncthreads();
    int NK = s_NK;

    // write: kept boxes in order, then suppressed in positional order w/ -1e30
    float* ob = out + (size_t)b * POST_NMS * 5;
    if (tid < PRE_NMS) {
        int incl = src[tid];
        int excl = incl - keepv;
        int slot; float sc;
        if (keepv) { slot = excl; sc = myScore; }
        else       { slot = NK + (tid - excl); sc = -1e30f; }
        if (slot < POST_NMS) {
            ob[slot * 5 + 0] = sb[tid * 4 + 0];
            ob[slot * 5 + 1] = sb[tid * 4 + 1];
            ob[slot * 5 + 2] = sb[tid * 4 + 2];
            ob[slot * 5 + 3] = sb[tid * 4 + 3];
            ob[slot * 5 + 4] = sc;
        }
    }
}

// ============================================================
extern "C" void kernel_launch(void* const* d_in, const int* in_sizes, int n_in,
                              void* d_out, int out_size)
{
    const float* x       = (const float*)d_in[0];
    const float* w_share = (const float*)d_in[1];
    const float* b_share = (const float*)d_in[2];
    const float* w_cls   = (const float*)d_in[3];
    const float* b_cls   = (const float*)d_in[4];
    const float* w_reg   = (const float*)d_in[5];
    const float* b_reg   = (const float*)d_in[6];
    float* out = (float*)d_out;

    cudaFuncSetAttribute(conv3x3_kernel, cudaFuncAttributeMaxDynamicSharedMemorySize, CONV_SMEM);
    cudaFuncSetAttribute(heads_decode_kernel, cudaFuncAttributeMaxDynamicSharedMemorySize, CIN * 32 * 4);
    cudaFuncSetAttribute(propose_kernel, cudaFuncAttributeMaxDynamicSharedMemorySize, PROP_SMEM);

    conv3x3_kernel<<<dim3(HH / 2, CIN / 64, BATCH), 256, CONV_SMEM>>>(x, w_share, b_share);
    heads_decode_kernel<<<dim3((NPX + 31) / 32, BATCH), 256, CIN * 32 * 4>>>(w_cls, b_cls, w_reg, b_reg);
    propose_kernel<<<BATCH, 1024, PROP_SMEM>>>(out);
}

// round 8
// speedup vs baseline: 1.1164x; 1.1164x over previous
#include <cuda_runtime.h>
#include <cuda_bf16.h>
#include <cstdint>

// ---------------- problem constants ----------------
#define BATCH 8
#define CIN 512
#define HH 50
#define WW 50
#define NPX (HH*WW)          // 2500
#define NA 9
#define NANCH (NPX*NA)       // 22500
#define PRE_NMS 1000
#define POST_NMS 300
#define NMS_THR 0.7f
#define IMGF 800.0f
#define MIN_SIZE 16.0f

// ---------------- device scratch (static; no allocations allowed) ----------------
__device__ float g_feat[(size_t)BATCH*CIN*NPX];     // shared conv output (relu'd)
__device__ float g_boxes[(size_t)BATCH*NANCH*4];
__device__ unsigned int g_key[(size_t)BATCH*NANCH]; // monotone score key (0 == invalid)

// ============================================================
// Kernel 1: 3x3 conv 512->512, SAME, +bias, ReLU, fp32
// Per-output FMA sequence over (chunk, c, dy, dx) identical to the
// round-3 passing kernel => bitwise identical conv output.
// block: 256 threads, tile 64 out-ch x (2 rows x 64 cols)
// thread: 4 consecutive k x (2 rows x 4 consecutive cols)
// smem: sIn [2][8][4][68]  (linear dest loads, float4 compute reads)
//       sW  [2][64][72]    (k-major: k*72 + c*9 + q; linear dest loads,
//                           scalar broadcast compute reads)
// ============================================================
#define IN_TILE (8*4*68)          // 2176 floats per buffer
#define W_TILE  (64*72)           // 4608 floats per buffer
#define CONV_SMEM (2*(IN_TILE + W_TILE)*4)   // 54272 bytes

__global__ __launch_bounds__(256, 2) void conv3x3_kernel(
    const float* __restrict__ x, const float* __restrict__ w, const float* __restrict__ bias)
{
    extern __shared__ float cs[];
    float* sIn = cs;               // buf*IN_TILE + c*272 + r*68 + xx
    float* sW  = cs + 2*IN_TILE;   // buf*W_TILE  + k*72 + c*9 + q

    const int r0 = blockIdx.x * 2;    // output row pair
    const int k0 = blockIdx.y * 64;
    const int b  = blockIdx.z;
    const int tid = threadIdx.x;
    const int kg = tid >> 4;          // 0..15 -> 4 consecutive k
    const int pxg = tid & 15;         // 0..15 -> 4 consecutive cols, 2 rows

    const float* xb = x + (size_t)b * CIN * NPX;
    const float* wk = w + (size_t)k0 * (CIN * 9);

    // ---- precompute input loader offsets (once) ----
    // input tile: 2176 elements = 8.5 * 256 -> 9 strided slots per thread
    int inoff[9];
#pragma unroll
    for (int t = 0; t < 9; ++t) {
        int idx = tid + 256 * t;
        if (idx < IN_TILE) {
            int c = idx / 272; int rem = idx % 272;
            int r = rem / 68;  int xx = rem % 68;
            int gy = r0 - 1 + r;
            int gx = xx - 1;
            bool ok = (xx < 66) && ((unsigned)gy < (unsigned)HH) && ((unsigned)gx < (unsigned)WW);
            inoff[t] = ok ? (c * NPX + gy * WW + gx) : -1;
        } else inoff[t] = -2;
    }

    auto load_chunk = [&](int ch, int buf) {
        float* dIn = sIn + buf * IN_TILE;
        float* dW  = sW  + buf * W_TILE;
        const int ginc = ch * 8 * NPX;
        const int winc = ch * 72;       // = ch*8*9, offset within a k-row of w
#pragma unroll
        for (int t = 0; t < 9; ++t) {
            int o = inoff[t];
            if (o != -2)
                dIn[tid + 256 * t] = (o >= 0) ? xb[ginc + o] : 0.f;
        }
        // weights: 4608 elements = 18 * 256, linear dest (k-major), coalesced src
#pragma unroll
        for (int t = 0; t < 18; ++t) {
            int lidx = tid + 256 * t;       // < 4608 always
            int kk = lidx / 72;             // const-divisor -> mul-high
            int rr = lidx - kk * 72;        // rr = c*9 + q
            dW[lidx] = wk[(size_t)kk * (CIN * 9) + winc + rr];
        }
    };

    float tot[4][8];
#pragma unroll
    for (int jj = 0; jj < 4; ++jj)
#pragma unroll
        for (int i = 0; i < 8; ++i) tot[jj][i] = 0.f;

    load_chunk(0, 0);
    __syncthreads();

    for (int ch = 0; ch < CIN / 8; ++ch) {
        const int cur = ch & 1;
        if (ch + 1 < CIN / 8) load_chunk(ch + 1, cur ^ 1);

        const float* bIn = sIn + cur * IN_TILE;
        const float* bW  = sW  + cur * W_TILE + kg * 4 * 72;   // this thread's 4 k rows

        float acc[4][8];
#pragma unroll
        for (int jj = 0; jj < 4; ++jj)
#pragma unroll
            for (int i = 0; i < 8; ++i) acc[jj][i] = 0.f;

#pragma unroll
        for (int c = 0; c < 8; ++c) {
            // load 4 input rows x 6 cols (vectorized, reused across dy/dx)
            float rows[4][6];
#pragma unroll
            for (int r = 0; r < 4; ++r) {
                const float4 v4 = *(const float4*)&bIn[c * 272 + r * 68 + 4 * pxg];
                const float2 v2 = *(const float2*)&bIn[c * 272 + r * 68 + 4 * pxg + 4];
                rows[r][0] = v4.x; rows[r][1] = v4.y; rows[r][2] = v4.z; rows[r][3] = v4.w;
                rows[r][4] = v2.x; rows[r][5] = v2.y;
            }
#pragma unroll
            for (int dy = 0; dy < 3; ++dy) {
#pragma unroll
                for (int dx = 0; dx < 3; ++dx) {
                    const int q = c * 9 + dy * 3 + dx;
                    float wv[4];
#pragma unroll
                    for (int jj = 0; jj < 4; ++jj)
                        wv[jj] = bW[jj * 72 + q];     // broadcast scalar LDS
#pragma unroll
                    for (int jj = 0; jj < 4; ++jj)
#pragma unroll
                        for (int ro = 0; ro < 2; ++ro)
#pragma unroll
                            for (int u = 0; u < 4; ++u)
                                acc[jj][ro * 4 + u] =
                                    fmaf(wv[jj], rows[ro + dy][u + dx], acc[jj][ro * 4 + u]);
                }
            }
        }
#pragma unroll
        for (int jj = 0; jj < 4; ++jj)
#pragma unroll
            for (int i = 0; i < 8; ++i) tot[jj][i] += acc[jj][i];

        __syncthreads();
    }

    // epilogue: bias + relu + store
#pragma unroll
    for (int ro = 0; ro < 2; ++ro) {
        int row = r0 + ro;
#pragma unroll
        for (int u = 0; u < 4; ++u) {
            int col = 4 * pxg + u;
            if (col < WW) {
#pragma unroll
                for (int jj = 0; jj < 4; ++jj) {
                    int k = k0 + kg * 4 + jj;
                    float v = tot[jj][ro * 4 + u] + bias[k];
                    v = fmaxf(v, 0.f);
                    g_feat[((size_t)b * CIN + k) * NPX + row * WW + col] = v;
                }
            }
        }
    }
}

// ============================================================
// Kernel 2: fused 1x1 heads (cls 18 + reg 36) + anchor decode.
// ============================================================
__global__ __launch_bounds__(256) void heads_decode_kernel(
    const float* __restrict__ wc, const float* __restrict__ bc,
    const float* __restrict__ wr, const float* __restrict__ brg)
{
    extern __shared__ float X[];            // [512][32]
    __shared__ float scls[32 * 18];
    __shared__ float sreg[32 * 36];

    const int b = blockIdx.y;
    const int p0 = blockIdx.x * 32;
    const int tid = threadIdx.x;

    for (int idx = tid; idx < CIN * 32; idx += 256) {
        int c = idx >> 5; int j = idx & 31;
        int p = p0 + j;
        X[idx] = (p < NPX) ? g_feat[((size_t)b * CIN + c) * NPX + p] : 0.f;
    }
    __syncthreads();

    for (int t = tid; t < 54 * 8; t += 256) {
        int o = t >> 3;
        int j0 = (t & 7) * 4;
        float bb = (o < 18) ? bc[o] : brg[o - 18];
        const float* W = (o < 18) ? (wc + (size_t)o * CIN) : (wr + (size_t)(o - 18) * CIN);
        float t0 = 0.f, t1 = 0.f, t2 = 0.f, t3 = 0.f;
        for (int cc = 0; cc < CIN; cc += 8) {
            float a0 = 0.f, a1 = 0.f, a2 = 0.f, a3 = 0.f;
#pragma unroll
            for (int u = 0; u < 8; ++u) {
                int c = cc + u;
                float wv = __ldg(&W[c]);
                const float4 xv = *(const float4*)&X[c * 32 + j0];
                a0 = fmaf(wv, xv.x, a0);
                a1 = fmaf(wv, xv.y, a1);
                a2 = fmaf(wv, xv.z, a2);
                a3 = fmaf(wv, xv.w, a3);
            }
            t0 += a0; t1 += a1; t2 += a2; t3 += a3;
        }
        float accs[4] = {t0 + bb, t1 + bb, t2 + bb, t3 + bb};
#pragma unroll
        for (int jj = 0; jj < 4; ++jj) {
            int j = j0 + jj;
            if (o < 18) scls[j * 18 + o] = accs[jj];
            else        sreg[j * 36 + (o - 18)] = accs[jj];
        }
    }
    __syncthreads();

    // decode 32*9 = 288 anchors
    for (int t = tid; t < 32 * NA; t += 256) {
        int j = t / NA;
        int a = t % NA;
        int p = p0 + j;
        if (p >= NPX) continue;
        int yy = p / WW;
        int xx = p % WW;

        int ri = a / 3, si = a % 3;
        float ratio = (ri == 0) ? 0.5f : (ri == 1 ? 1.0f : 2.0f);
        float scale = (si == 0) ? 8.0f : (si == 1 ? 16.0f : 32.0f);
        float ah = 16.0f * scale * sqrtf(ratio);
        float aw = 16.0f * scale * sqrtf(1.0f / ratio);
        float sy = yy * 16.0f, sx = xx * 16.0f;
        float ay1 = sy + 8.0f - ah * 0.5f;
        float ax1 = sx + 8.0f - aw * 0.5f;
        float ay2 = sy + 8.0f + ah * 0.5f;
        float ax2 = sx + 8.0f + aw * 0.5f;

        float h = ay2 - ay1;
        float w = ax2 - ax1;
        float cy = ay1 + 0.5f * h;
        float cx = ax1 + 0.5f * w;

        const float* rg = &sreg[j * 36 + a * 4];
        float ncy = rg[0] * h + cy;
        float ncx = rg[1] * w + cx;
        float nh = h * expf(rg[2]);
        float nw = w * expf(rg[3]);

        float y1 = fminf(fmaxf(ncy - 0.5f * nh, 0.f), IMGF);
        float x1 = fminf(fmaxf(ncx - 0.5f * nw, 0.f), IMGF);
        float y2 = fminf(fmaxf(ncy + 0.5f * nh, 0.f), IMGF);
        float x2 = fminf(fmaxf(ncx + 0.5f * nw, 0.f), IMGF);

        float hs = y2 - y1, ws = x2 - x1;
        bool valid = (hs >= MIN_SIZE) && (ws >= MIN_SIZE);

        float c0 = scls[j * 18 + a * 2 + 0], c1 = scls[j * 18 + a * 2 + 1];
        float m = fmaxf(c0, c1);
        float e0 = expf(c0 - m);
        float e1 = expf(c1 - m);
        float score = e1 / (e0 + e1);

        int n = p * NA + a;
        float* bx = &g_boxes[((size_t)b * NANCH + n) * 4];
        bx[0] = y1; bx[1] = x1; bx[2] = y2; bx[3] = x2;
        g_key[(size_t)b * NANCH + n] = valid ? (__float_as_uint(score) | 0x80000000u) : 0u;
    }
}

// ============================================================
// Kernel 3: per-image top-1000 select + sort + bitmask NMS + top-300 output
// ============================================================
#define PROP_SMEM 160256

__global__ __launch_bounds__(1024) void propose_kernel(float* __restrict__ out)
{
    extern __shared__ unsigned char smem[];
    unsigned int* skey = (unsigned int*)smem;
    unsigned long long* cand = (unsigned long long*)(smem + 90112);
    float* sb     = (float*)smem;
    float* sarea  = (float*)(smem + 16000);
    float* sscore = (float*)(smem + 20000);
    unsigned int* mask = (unsigned int*)(smem + 24000);
    int* sA = (int*)(smem + 152064);
    int* sB = (int*)(smem + 152064 + 4096);
    __shared__ int s_cnt;
    __shared__ unsigned int s_T;
    __shared__ int s_nc;
    __shared__ int s_NK;
    __shared__ unsigned int kw[32];

    const int b = blockIdx.x;
    const int tid = threadIdx.x;
    const int wid = tid >> 5;
    const int lane = tid & 31;
    const unsigned int* gk = g_key + (size_t)b * NANCH;

    for (int n = tid; n < NANCH; n += 1024) skey[n] = gk[n];
    if (tid == 0) s_T = 0u;
    __syncthreads();

    for (int bit = 31; bit >= 0; --bit) {
        unsigned int T2 = s_T | (1u << bit);
        if (tid == 0) s_cnt = 0;
        __syncthreads();
        int c = 0;
        for (int n = tid; n < NANCH; n += 1024) c += (skey[n] >= T2) ? 1 : 0;
#pragma unroll
        for (int o = 16; o; o >>= 1) c += __shfl_down_sync(0xFFFFFFFFu, c, o);
        if (lane == 0) atomicAdd(&s_cnt, c);
        __syncthreads();
        if (tid == 0 && s_cnt >= PRE_NMS) s_T = T2;
        __syncthreads();
    }
    unsigned int T = s_T;
    if (tid == 0) s_nc = 0;
    __syncthreads();

    for (int n = tid; n < NANCH; n += 1024) {
        unsigned int k = skey[n];
        if (k >= T) {
            int pos = atomicAdd(&s_nc, 1);
            if (pos < 2048)
                cand[pos] = ((unsigned long long)k << 32) | (unsigned int)(~n);
        }
    }
    __syncthreads();
    int nc = min(s_nc, 2048);
    for (int i = tid; i < 2048; i += 1024)
        if (i >= nc) cand[i] = 0ull;
    __syncthreads();

    for (int k = 2; k <= 2048; k <<= 1) {
        for (int j = k >> 1; j > 0; j >>= 1) {
            __syncthreads();
#pragma unroll
            for (int base = 0; base < 2048; base += 1024) {
                int i = base + tid;
                int ixj = i ^ j;
                if (ixj > i) {
                    unsigned long long a = cand[i], c2 = cand[ixj];
                    bool up = ((i & k) == 0);
                    bool swap = up ? (a < c2) : (a > c2);
                    if (swap) { cand[i] = c2; cand[ixj] = a; }
                }
            }
        }
    }
    __syncthreads();

    float myScore = 0.f;
    if (tid < PRE_NMS) {
        unsigned long long ck = cand[tid];
        unsigned int idx = ~(unsigned int)(ck & 0xFFFFFFFFull);
        if (idx >= (unsigned)NANCH) idx = 0;
        const float* bx = g_boxes + ((size_t)b * NANCH + idx) * 4;
        float y1 = bx[0], x1 = bx[1], y2 = bx[2], x2 = bx[3];
        sb[tid * 4 + 0] = y1; sb[tid * 4 + 1] = x1;
        sb[tid * 4 + 2] = y2; sb[tid * 4 + 3] = x2;
        sarea[tid] = (y2 - y1) * (x2 - x1);
        unsigned int kb = (unsigned int)(ck >> 32);
        myScore = __uint_as_float(kb ^ 0x80000000u);
        sscore[tid] = myScore;
    }
    __syncthreads();

    for (int i = wid; i < PRE_NMS; i += 32) {
        const float4 bi = ((const float4*)sb)[i];
        const float ai = sarea[i];
#pragma unroll 4
        for (int w0 = 0; w0 < 32; ++w0) {
            int j = w0 * 32 + lane;
            bool sup = false;
            if (j > i && j < PRE_NMS) {
                const float4 bj = ((const float4*)sb)[j];
                float ty = fmaxf(bi.x, bj.x);
                float tx = fmaxf(bi.y, bj.y);
                float by = fminf(bi.z, bj.z);
                float bxx = fminf(bi.w, bj.w);
                float ih = fmaxf(by - ty, 0.f);
                float iw = fmaxf(bxx - tx, 0.f);
                float inter = ih * iw;
                float iou = inter / (ai + sarea[j] - inter + 1e-9f);
                sup = iou > NMS_THR;
            }
            unsigned int word = __ballot_sync(0xFFFFFFFFu, sup);
            if (lane == 0) mask[i * 32 + w0] = word;
        }
    }
    if (tid < 32) kw[tid] = 0xFFFFFFFFu;
    __syncthreads();

    if (tid < 32) {
        for (int i = 0; i < PRE_NMS; ++i) {
            unsigned int w = kw[i >> 5];
            if ((w >> (i & 31)) & 1u)
                kw[tid] &= ~mask[i * 32 + tid];
            __syncwarp();
        }
    }
    __syncthreads();

    int keepv = (tid < PRE_NMS) ? (int)((kw[tid >> 5] >> (tid & 31)) & 1u) : 0;
    sA[tid] = keepv;
    __syncthreads();
    int* src = sA; int* dst = sB;
    for (int d = 1; d < 1024; d <<= 1) {
        int v = src[tid];
        if (tid >= d) v += src[tid - d];
        dst[tid] = v;
        __syncthreads();
        int* t = src; src = dst; dst = t;
    }
    if (tid == 0) s_NK = src[PRE_NMS - 1];
    __syncthreads();
    int NK = s_NK;

    float* ob = out + (size_t)b * POST_NMS * 5;
    if (tid < PRE_NMS) {
        int incl = src[tid];
        int excl = incl - keepv;
        int slot; float sc;
        if (keepv) { slot = excl; sc = myScore; }
        else       { slot = NK + (tid - excl); sc = -1e30f; }
        if (slot < POST_NMS) {
            ob[slot * 5 + 0] = sb[tid * 4 + 0];
            ob[slot * 5 + 1] = sb[tid * 4 + 1];
            ob[slot * 5 + 2] = sb[tid * 4 + 2];
            ob[slot * 5 + 3] = sb[tid * 4 + 3];
            ob[slot * 5 + 4] = sc;
        }
    }
}

// ============================================================
extern "C" void kernel_launch(void* const* d_in, const int* in_sizes, int n_in,
                              void* d_out, int out_size)
{
    const float* x       = (const float*)d_in[0];
    const float* w_share = (const float*)d_in[1];
    const float* b_share = (const float*)d_in[2];
    const float* w_cls   = (const float*)d_in[3];
    const float* b_cls   = (const float*)d_in[4];
    const float* w_reg   = (const float*)d_in[5];
    const float* b_reg   = (const float*)d_in[6];
    float* out = (float*)d_out;

    cudaFuncSetAttribute(conv3x3_kernel, cudaFuncAttributeMaxDynamicSharedMemorySize, CONV_SMEM);
    cudaFuncSetAttribute(heads_decode_kernel, cudaFuncAttributeMaxDynamicSharedMemorySize, CIN * 32 * 4);
    cudaFuncSetAttribute(propose_kernel, cudaFuncAttributeMaxDynamicSharedMemorySize, PROP_SMEM);

    conv3x3_kernel<<<dim3(HH / 2, CIN / 64, BATCH), 256, CONV_SMEM>>>(x, w_share, b_share);
    heads_decode_kernel<<<dim3((NPX + 31) / 32, BATCH), 256, CIN * 32 * 4>>>(w_cls, b_cls, w_reg, b_reg);
    propose_kernel<<<BATCH, 1024, PROP_SMEM>>>(out);
}

// round 9
// speedup vs baseline: 1.1419x; 1.0229x over previous
#include <cuda_runtime.h>
#include <cuda_bf16.h>
#include <cstdint>

// ---------------- problem constants ----------------
#define BATCH 8
#define CIN 512
#define HH 50
#define WW 50
#define NPX (HH*WW)          // 2500
#define NA 9
#define NANCH (NPX*NA)       // 22500
#define PRE_NMS 1000
#define POST_NMS 300
#define NMS_THR 0.7f
#define IMGF 800.0f
#define MIN_SIZE 16.0f

// ---------------- device scratch (static; no allocations allowed) ----------------
__device__ float g_feat[(size_t)BATCH*CIN*NPX];     // shared conv output (relu'd)
__device__ float g_boxes[(size_t)BATCH*NANCH*4];
__device__ unsigned int g_key[(size_t)BATCH*NANCH]; // monotone score key (0 == invalid)

// ============================================================
// Kernel 1: 3x3 conv 512->512, SAME, +bias, ReLU, fp32
// FMA sequence over (chunk, c, dy, dx) identical to round-3 passing
// kernel => bitwise identical output.
// block: 256 threads, tile 64 out-ch x (2 rows x 64 cols)
// thread: 4 consecutive k x (2 rows x 4 consecutive cols)
// smem: sIn [2][8][4][68]   input, float4 compute reads
//       sW  [2][8][9][68]   weights [c][q][64k + 4 pad]:
//                           float4 compute reads (4 consecutive k),
//                           loaded via register-staged transpose
//                           (coalesced float4 LDG + padded-scatter STS)
// ============================================================
#define IN_TILE (8*4*68)          // 2176 floats per buffer
#define W_TILE  (8*9*68)          // 4896 floats per buffer
#define CONV_SMEM (2*(IN_TILE + W_TILE)*4)   // 56576 bytes

__global__ __launch_bounds__(256, 2) void conv3x3_kernel(
    const float* __restrict__ x, const float* __restrict__ w, const float* __restrict__ bias)
{
    extern __shared__ float cs[];
    float* sIn = cs;               // buf*IN_TILE + c*272 + r*68 + xx
    float* sW  = cs + 2*IN_TILE;   // buf*W_TILE  + c*612 + q*68 + k

    const int r0 = blockIdx.x * 2;    // output row pair
    const int k0 = blockIdx.y * 64;
    const int b  = blockIdx.z;
    const int tid = threadIdx.x;
    const int kg = tid >> 4;          // 0..15 -> 4 consecutive k
    const int pxg = tid & 15;         // 0..15 -> 4 consecutive cols, 2 rows

    const float* xb = x + (size_t)b * CIN * NPX;
    const float* wk = w + (size_t)k0 * (CIN * 9);

    // ---- precompute input loader offsets (once) ----
    int inoff[9];
#pragma unroll
    for (int t = 0; t < 9; ++t) {
        int idx = tid + 256 * t;
        if (idx < IN_TILE) {
            int c = idx / 272; int rem = idx % 272;
            int r = rem / 68;  int xx = rem % 68;
            int gy = r0 - 1 + r;
            int gx = xx - 1;
            bool ok = (xx < 66) && ((unsigned)gy < (unsigned)HH) && ((unsigned)gx < (unsigned)WW);
            inoff[t] = ok ? (c * NPX + gy * WW + gx) : -1;
        } else inoff[t] = -2;
    }

    auto load_chunk = [&](int ch, int buf) {
        float* dIn = sIn + buf * IN_TILE;
        float* dW  = sW  + buf * W_TILE;
        const int ginc = ch * 8 * NPX;
        const int winc = ch * 72;       // offset within a k-row of w (floats)
#pragma unroll
        for (int t = 0; t < 9; ++t) {
            int o = inoff[t];
            if (o != -2)
                dIn[tid + 256 * t] = (o >= 0) ? xb[ginc + o] : 0.f;
        }
        // weights: 64 k-rows x 72 floats = 1152 float4, coalesced LDG then
        // transpose-scatter into [c][q][68] (k fastest, padded rows)
#pragma unroll
        for (int t = 0; t < 5; ++t) {
            int v4 = tid + 256 * t;
            if (v4 < 1152) {
                int kk = v4 / 18;               // const-divisor
                int f  = v4 - kk * 18;          // float4 index within k-row
                const float4 wv = *(const float4*)&wk[(size_t)kk * (CIN * 9) + winc + f * 4];
                const float vals[4] = {wv.x, wv.y, wv.z, wv.w};
#pragma unroll
                for (int j = 0; j < 4; ++j) {
                    int e = f * 4 + j;          // 0..71 = c*9 + q
                    int c = e / 9;
                    int q = e - c * 9;
                    dW[c * 612 + q * 68 + kk] = vals[j];
                }
            }
        }
    };

    float tot[4][8];
#pragma unroll
    for (int jj = 0; jj < 4; ++jj)
#pragma unroll
        for (int i = 0; i < 8; ++i) tot[jj][i] = 0.f;

    load_chunk(0, 0);
    __syncthreads();

    for (int ch = 0; ch < CIN / 8; ++ch) {
        const int cur = ch & 1;
        if (ch + 1 < CIN / 8) load_chunk(ch + 1, cur ^ 1);

        const float* bIn = sIn + cur * IN_TILE;
        const float* bW  = sW  + cur * W_TILE + kg * 4;   // this thread's 4 k

        float acc[4][8];
#pragma unroll
        for (int jj = 0; jj < 4; ++jj)
#pragma unroll
            for (int i = 0; i < 8; ++i) acc[jj][i] = 0.f;

#pragma unroll
        for (int c = 0; c < 8; ++c) {
            // load 4 input rows x 6 cols (vectorized, reused across dy/dx)
            float rows[4][6];
#pragma unroll
            for (int r = 0; r < 4; ++r) {
                const float4 v4 = *(const float4*)&bIn[c * 272 + r * 68 + 4 * pxg];
                const float2 v2 = *(const float2*)&bIn[c * 272 + r * 68 + 4 * pxg + 4];
                rows[r][0] = v4.x; rows[r][1] = v4.y; rows[r][2] = v4.z; rows[r][3] = v4.w;
                rows[r][4] = v2.x; rows[r][5] = v2.y;
            }
#pragma unroll
            for (int dy = 0; dy < 3; ++dy) {
#pragma unroll
                for (int dx = 0; dx < 3; ++dx) {
                    const float4 wq = *(const float4*)&bW[c * 612 + (dy * 3 + dx) * 68];
                    const float wv[4] = {wq.x, wq.y, wq.z, wq.w};
#pragma unroll
                    for (int jj = 0; jj < 4; ++jj)
#pragma unroll
                        for (int ro = 0; ro < 2; ++ro)
#pragma unroll
                            for (int u = 0; u < 4; ++u)
                                acc[jj][ro * 4 + u] =
                                    fmaf(wv[jj], rows[ro + dy][u + dx], acc[jj][ro * 4 + u]);
                }
            }
        }
#pragma unroll
        for (int jj = 0; jj < 4; ++jj)
#pragma unroll
            for (int i = 0; i < 8; ++i) tot[jj][i] += acc[jj][i];

        __syncthreads();
    }

    // epilogue: bias + relu + store
#pragma unroll
    for (int ro = 0; ro < 2; ++ro) {
        int row = r0 + ro;
#pragma unroll
        for (int u = 0; u < 4; ++u) {
            int col = 4 * pxg + u;
            if (col < WW) {
#pragma unroll
                for (int jj = 0; jj < 4; ++jj) {
                    int k = k0 + kg * 4 + jj;
                    float v = tot[jj][ro * 4 + u] + bias[k];
                    v = fmaxf(v, 0.f);
                    g_feat[((size_t)b * CIN + k) * NPX + row * WW + col] = v;
                }
            }
        }
    }
}

// ============================================================
// Kernel 2: fused 1x1 heads (cls 18 + reg 36) + anchor decode.
// ============================================================
__global__ __launch_bounds__(256) void heads_decode_kernel(
    const float* __restrict__ wc, const float* __restrict__ bc,
    const float* __restrict__ wr, const float* __restrict__ brg)
{
    extern __shared__ float X[];            // [512][32]
    __shared__ float scls[32 * 18];
    __shared__ float sreg[32 * 36];

    const int b = blockIdx.y;
    const int p0 = blockIdx.x * 32;
    const int tid = threadIdx.x;

    for (int idx = tid; idx < CIN * 32; idx += 256) {
        int c = idx >> 5; int j = idx & 31;
        int p = p0 + j;
        X[idx] = (p < NPX) ? g_feat[((size_t)b * CIN + c) * NPX + p] : 0.f;
    }
    __syncthreads();

    for (int t = tid; t < 54 * 8; t += 256) {
        int o = t >> 3;
        int j0 = (t & 7) * 4;
        float bb = (o < 18) ? bc[o] : brg[o - 18];
        const float* W = (o < 18) ? (wc + (size_t)o * CIN) : (wr + (size_t)(o - 18) * CIN);
        float t0 = 0.f, t1 = 0.f, t2 = 0.f, t3 = 0.f;
        for (int cc = 0; cc < CIN; cc += 8) {
            float a0 = 0.f, a1 = 0.f, a2 = 0.f, a3 = 0.f;
#pragma unroll
            for (int u = 0; u < 8; ++u) {
                int c = cc + u;
                float wv = __ldg(&W[c]);
                const float4 xv = *(const float4*)&X[c * 32 + j0];
                a0 = fmaf(wv, xv.x, a0);
                a1 = fmaf(wv, xv.y, a1);
                a2 = fmaf(wv, xv.z, a2);
                a3 = fmaf(wv, xv.w, a3);
            }
            t0 += a0; t1 += a1; t2 += a2; t3 += a3;
        }
        float accs[4] = {t0 + bb, t1 + bb, t2 + bb, t3 + bb};
#pragma unroll
        for (int jj = 0; jj < 4; ++jj) {
            int j = j0 + jj;
            if (o < 18) scls[j * 18 + o] = accs[jj];
            else        sreg[j * 36 + (o - 18)] = accs[jj];
        }
    }
    __syncthreads();

    // decode 32*9 = 288 anchors
    for (int t = tid; t < 32 * NA; t += 256) {
        int j = t / NA;
        int a = t % NA;
        int p = p0 + j;
        if (p >= NPX) continue;
        int yy = p / WW;
        int xx = p % WW;

        int ri = a / 3, si = a % 3;
        float ratio = (ri == 0) ? 0.5f : (ri == 1 ? 1.0f : 2.0f);
        float scale = (si == 0) ? 8.0f : (si == 1 ? 16.0f : 32.0f);
        float ah = 16.0f * scale * sqrtf(ratio);
        float aw = 16.0f * scale * sqrtf(1.0f / ratio);
        float sy = yy * 16.0f, sx = xx * 16.0f;
        float ay1 = sy + 8.0f - ah * 0.5f;
        float ax1 = sx + 8.0f - aw * 0.5f;
        float ay2 = sy + 8.0f + ah * 0.5f;
        float ax2 = sx + 8.0f + aw * 0.5f;

        float h = ay2 - ay1;
        float w = ax2 - ax1;
        float cy = ay1 + 0.5f * h;
        float cx = ax1 + 0.5f * w;

        const float* rg = &sreg[j * 36 + a * 4];
        float ncy = rg[0] * h + cy;
        float ncx = rg[1] * w + cx;
        float nh = h * expf(rg[2]);
        float nw = w * expf(rg[3]);

        float y1 = fminf(fmaxf(ncy - 0.5f * nh, 0.f), IMGF);
        float x1 = fminf(fmaxf(ncx - 0.5f * nw, 0.f), IMGF);
        float y2 = fminf(fmaxf(ncy + 0.5f * nh, 0.f), IMGF);
        float x2 = fminf(fmaxf(ncx + 0.5f * nw, 0.f), IMGF);

        float hs = y2 - y1, ws = x2 - x1;
        bool valid = (hs >= MIN_SIZE) && (ws >= MIN_SIZE);

        float c0 = scls[j * 18 + a * 2 + 0], c1 = scls[j * 18 + a * 2 + 1];
        float m = fmaxf(c0, c1);
        float e0 = expf(c0 - m);
        float e1 = expf(c1 - m);
        float score = e1 / (e0 + e1);

        int n = p * NA + a;
        float* bx = &g_boxes[((size_t)b * NANCH + n) * 4];
        bx[0] = y1; bx[1] = x1; bx[2] = y2; bx[3] = x2;
        g_key[(size_t)b * NANCH + n] = valid ? (__float_as_uint(score) | 0x80000000u) : 0u;
    }
}

// ============================================================
// Kernel 3: per-image top-1000 select + sort + bitmask NMS + top-300 output
// ============================================================
#define PROP_SMEM 160256

__global__ __launch_bounds__(1024) void propose_kernel(float* __restrict__ out)
{
    extern __shared__ unsigned char smem[];
    unsigned int* skey = (unsigned int*)smem;
    unsigned long long* cand = (unsigned long long*)(smem + 90112);
    float* sb     = (float*)smem;
    float* sarea  = (float*)(smem + 16000);
    float* sscore = (float*)(smem + 20000);
    unsigned int* mask = (unsigned int*)(smem + 24000);
    int* sA = (int*)(smem + 152064);
    int* sB = (int*)(smem + 152064 + 4096);
    __shared__ int s_cnt;
    __shared__ unsigned int s_T;
    __shared__ int s_nc;
    __shared__ int s_NK;
    __shared__ unsigned int kw[32];

    const int b = blockIdx.x;
    const int tid = threadIdx.x;
    const int wid = tid >> 5;
    const int lane = tid & 31;
    const unsigned int* gk = g_key + (size_t)b * NANCH;

    for (int n = tid; n < NANCH; n += 1024) skey[n] = gk[n];
    if (tid == 0) s_T = 0u;
    __syncthreads();

    for (int bit = 31; bit >= 0; --bit) {
        unsigned int T2 = s_T | (1u << bit);
        if (tid == 0) s_cnt = 0;
        __syncthreads();
        int c = 0;
        for (int n = tid; n < NANCH; n += 1024) c += (skey[n] >= T2) ? 1 : 0;
#pragma unroll
        for (int o = 16; o; o >>= 1) c += __shfl_down_sync(0xFFFFFFFFu, c, o);
        if (lane == 0) atomicAdd(&s_cnt, c);
        __syncthreads();
        if (tid == 0 && s_cnt >= PRE_NMS) s_T = T2;
        __syncthreads();
    }
    unsigned int T = s_T;
    if (tid == 0) s_nc = 0;
    __syncthreads();

    for (int n = tid; n < NANCH; n += 1024) {
        unsigned int k = skey[n];
        if (k >= T) {
            int pos = atomicAdd(&s_nc, 1);
            if (pos < 2048)
                cand[pos] = ((unsigned long long)k << 32) | (unsigned int)(~n);
        }
    }
    __syncthreads();
    int nc = min(s_nc, 2048);
    for (int i = tid; i < 2048; i += 1024)
        if (i >= nc) cand[i] = 0ull;
    __syncthreads();

    for (int k = 2; k <= 2048; k <<= 1) {
        for (int j = k >> 1; j > 0; j >>= 1) {
            __syncthreads();
#pragma unroll
            for (int base = 0; base < 2048; base += 1024) {
                int i = base + tid;
                int ixj = i ^ j;
                if (ixj > i) {
                    unsigned long long a = cand[i], c2 = cand[ixj];
                    bool up = ((i & k) == 0);
                    bool swap = up ? (a < c2) : (a > c2);
                    if (swap) { cand[i] = c2; cand[ixj] = a; }
                }
            }
        }
    }
    __syncthreads();

    float myScore = 0.f;
    if (tid < PRE_NMS) {
        unsigned long long ck = cand[tid];
        unsigned int idx = ~(unsigned int)(ck & 0xFFFFFFFFull);
        if (idx >= (unsigned)NANCH) idx = 0;
        const float* bx = g_boxes + ((size_t)b * NANCH + idx) * 4;
        float y1 = bx[0], x1 = bx[1], y2 = bx[2], x2 = bx[3];
        sb[tid * 4 + 0] = y1; sb[tid * 4 + 1] = x1;
        sb[tid * 4 + 2] = y2; sb[tid * 4 + 3] = x2;
        sarea[tid] = (y2 - y1) * (x2 - x1);
        unsigned int kb = (unsigned int)(ck >> 32);
        myScore = __uint_as_float(kb ^ 0x80000000u);
        sscore[tid] = myScore;
    }
    __syncthreads();

    for (int i = wid; i < PRE_NMS; i += 32) {
        const float4 bi = ((const float4*)sb)[i];
        const float ai = sarea[i];
#pragma unroll 4
        for (int w0 = 0; w0 < 32; ++w0) {
            int j = w0 * 32 + lane;
            bool sup = false;
            if (j > i && j < PRE_NMS) {
                const float4 bj = ((const float4*)sb)[j];
                float ty = fmaxf(bi.x, bj.x);
                float tx = fmaxf(bi.y, bj.y);
                float by = fminf(bi.z, bj.z);
                float bxx = fminf(bi.w, bj.w);
                float ih = fmaxf(by - ty, 0.f);
                float iw = fmaxf(bxx - tx, 0.f);
                float inter = ih * iw;
                float iou = inter / (ai + sarea[j] - inter + 1e-9f);
                sup = iou > NMS_THR;
            }
            unsigned int word = __ballot_sync(0xFFFFFFFFu, sup);
            if (lane == 0) mask[i * 32 + w0] = word;
        }
    }
    if (tid < 32) kw[tid] = 0xFFFFFFFFu;
    __syncthreads();

    if (tid < 32) {
        for (int i = 0; i < PRE_NMS; ++i) {
            unsigned int w = kw[i >> 5];
            if ((w >> (i & 31)) & 1u)
                kw[tid] &= ~mask[i * 32 + tid];
            __syncwarp();
        }
    }
    __syncthreads();

    int keepv = (tid < PRE_NMS) ? (int)((kw[tid >> 5] >> (tid & 31)) & 1u) : 0;
    sA[tid] = keepv;
    __syncthreads();
    int* src = sA; int* dst = sB;
    for (int d = 1; d < 1024; d <<= 1) {
        int v = src[tid];
        if (tid >= d) v += src[tid - d];
        dst[tid] = v;
        __syncthreads();
        int* t = src; src = dst; dst = t;
    }
    if (tid == 0) s_NK = src[PRE_NMS - 1];
    __syncthreads();
    int NK = s_NK;

    float* ob = out + (size_t)b * POST_NMS * 5;
    if (tid < PRE_NMS) {
        int incl = src[tid];
        int excl = incl - keepv;
        int slot; float sc;
        if (keepv) { slot = excl; sc = myScore; }
        else       { slot = NK + (tid - excl); sc = -1e30f; }
        if (slot < POST_NMS) {
            ob[slot * 5 + 0] = sb[tid * 4 + 0];
            ob[slot * 5 + 1] = sb[tid * 4 + 1];
            ob[slot * 5 + 2] = sb[tid * 4 + 2];
            ob[slot * 5 + 3] = sb[tid * 4 + 3];
            ob[slot * 5 + 4] = sc;
        }
    }
}

// ============================================================
extern "C" void kernel_launch(void* const* d_in, const int* in_sizes, int n_in,
                              void* d_out, int out_size)
{
    const float* x       = (const float*)d_in[0];
    const float* w_share = (const float*)d_in[1];
    const float* b_share = (const float*)d_in[2];
    const float* w_cls   = (const float*)d_in[3];
    const float* b_cls   = (const float*)d_in[4];
    const float* w_reg   = (const float*)d_in[5];
    const float* b_reg   = (const float*)d_in[6];
    float* out = (float*)d_out;

    cudaFuncSetAttribute(conv3x3_kernel, cudaFuncAttributeMaxDynamicSharedMemorySize, CONV_SMEM);
    cudaFuncSetAttribute(heads_decode_kernel, cudaFuncAttributeMaxDynamicSharedMemorySize, CIN * 32 * 4);
    cudaFuncSetAttribute(propose_kernel, cudaFuncAttributeMaxDynamicSharedMemorySize, PROP_SMEM);

    conv3x3_kernel<<<dim3(HH / 2, CIN / 64, BATCH), 256, CONV_SMEM>>>(x, w_share, b_share);
    heads_decode_kernel<<<dim3((NPX + 31) / 32, BATCH), 256, CIN * 32 * 4>>>(w_cls, b_cls, w_reg, b_reg);
    propose_kernel<<<BATCH, 1024, PROP_SMEM>>>(out);
}